// round 15
// baseline (speedup 1.0000x reference)
#include <cuda_runtime.h>
#include <cuda_bf16.h>
#include <stdint.h>
#include <math.h>

#define NB 8
#define NC 64
#define NN 4000
#define TI 128          // i-tile rows
#define TJS 64          // j-subtile width
#define NSUB 3          // j-subtiles per block (strip = 192; smem 46.1KB < 48KB)
#define JTS 21          // ceil(4000/192) j-strips per mode
#define IT32 32         // ceil(4000/128) i-tiles
#define TOTAL_BLOCKS (2 * JTS * IT32 * NB)
#define SMSTRIDE 72     // 64 bf16 + 8 pad (144B rows; ldmatrix conflict-free)
#define PER 16          // indices per thread in compact

// Scratch (device globals; no allocations allowed)
__device__ __nv_bfloat16 g_feat2[NB * NN * NC];  // normalized, COMPACTED order
__device__ int           g_pmap[NB * NN];
__device__ int           g_cnt[NB];
__device__ double        g_pos[NB];
__device__ double        g_neg[NB];
__device__ unsigned      g_done;                 // completion counter (self-resets)

// ---------------------------------------------------------------------------
// Kernel 1: classify + position map via ONE block-scan (deterministic).
// ---------------------------------------------------------------------------
__global__ void compact_kernel(const float* __restrict__ prob) {
    int b = blockIdx.x;
    int tid = threadIdx.x;
    int lane = tid & 31, wid = tid >> 5;
    int start = tid * PER;

    const float* pb = prob + b * NN;
    unsigned mask = 0;
    int cN = 0;
#pragma unroll
    for (int k = 0; k < PER; k++) {
        int idx = start + k;
        if (idx < NN && pb[idx] < 0.5f) { mask |= (1u << k); cN++; }
    }
    int nv = (start < NN) ? min(PER, NN - start) : 0;
    int cA = nv - cN;

    int sNi = cN, sAi = cA;
#pragma unroll
    for (int o = 1; o < 32; o <<= 1) {
        int xn = __shfl_up_sync(0xffffffffu, sNi, o);
        int xa = __shfl_up_sync(0xffffffffu, sAi, o);
        if (lane >= o) { sNi += xn; sAi += xa; }
    }
    __shared__ int wN[8], wA[8];
    if (lane == 31) { wN[wid] = sNi; wA[wid] = sAi; }
    __syncthreads();
    int baseWN = 0, baseWA = 0, totN = 0;
    for (int w = 0; w < 8; w++) {
        if (w < wid) { baseWN += wN[w]; baseWA += wA[w]; }
        totN += wN[w];
    }
    int offN = baseWN + sNi - cN;
    int offA = baseWA + sAi - cA;

    int* pm = g_pmap + b * NN;
#pragma unroll
    for (int k = 0; k < PER; k++) {
        int idx = start + k;
        if (idx >= NN) break;
        if (mask & (1u << k)) pm[idx] = offN++;
        else                  pm[idx] = ~(offA++);
    }
    if (tid == 0) {
        g_cnt[b] = totN;
        g_pos[b] = 0.0;
        g_neg[b] = 0.0;
    }
}

// ---------------------------------------------------------------------------
// Kernel 2: row-normalize (fp32) -> bf16, writing to COMPACTED row position.
// ---------------------------------------------------------------------------
__global__ void normalize_kernel(const float* __restrict__ feat) {
    int row = blockIdx.x * blockDim.x + threadIdx.x;
    if (row >= NB * NN) return;
    int b = row / NN;
    int n = row - b * NN;
    const float* src = feat + (size_t)b * NC * NN + n;
    float v[NC];
    float ss = 0.f;
#pragma unroll
    for (int c = 0; c < NC; c++) {
        float x = src[(size_t)c * NN];
        v[c] = x;
        ss += x * x;
    }
    float inv = 1.0f / fmaxf(sqrtf(ss), 1e-12f);
    int pm = g_pmap[b * NN + n];
    int dstRow = (pm >= 0) ? pm : (g_cnt[b] + ~pm);
    __nv_bfloat16* dst = g_feat2 + ((size_t)b * NN + dstRow) * NC;
#pragma unroll
    for (int c = 0; c < NC; c++) dst[c] = __float2bfloat16(v[c] * inv);
}

// ---------------------------------------------------------------------------
// Fused GEMM + loss + inline finalize (last block via completion counter).
// mode 0: upper triangle, sum exp, x2.  mode 1: softplus, 8-way log-product.
// Staged cp.async groups: sub0 compute overlaps B1/B2 fills.
// ---------------------------------------------------------------------------
__device__ __forceinline__ void cpa16(unsigned dst, const void* src, bool valid) {
    int sz = valid ? 16 : 0;
    asm volatile("cp.async.cg.shared.global [%0], [%1], 16, %2;\n"
                 :: "r"(dst), "l"(src), "r"(sz));
}
__device__ __forceinline__ void ldm_x4(unsigned r[4], unsigned addr) {
    asm volatile("ldmatrix.sync.aligned.m8n8.x4.shared.b16 {%0,%1,%2,%3}, [%4];\n"
                 : "=r"(r[0]), "=r"(r[1]), "=r"(r[2]), "=r"(r[3]) : "r"(addr));
}
__device__ __forceinline__ void mma_bf16(float d[4], const unsigned a[4],
                                         unsigned b0, unsigned b1) {
    asm volatile(
        "mma.sync.aligned.m16n8k16.row.col.f32.bf16.bf16.f32 "
        "{%0,%1,%2,%3}, {%4,%5,%6,%7}, {%8,%9}, {%0,%1,%2,%3};\n"
        : "+f"(d[0]), "+f"(d[1]), "+f"(d[2]), "+f"(d[3])
        : "r"(a[0]), "r"(a[1]), "r"(a[2]), "r"(a[3]), "r"(b0), "r"(b1));
}

__global__ __launch_bounds__(256, 3) void mma_loss_kernel(float* __restrict__ out) {
    int b = blockIdx.z;
    int nI = g_cnt[b];
    int mode = (blockIdx.x >= JTS) ? 1 : 0;
    int jt = blockIdx.x - mode * JTS;
    int nJ = mode ? (NN - nI) : nI;
    int i0 = blockIdx.y * TI;
    int j0 = jt * (TJS * NSUB);

    __shared__ __nv_bfloat16 As[TI][SMSTRIDE];
    __shared__ __nv_bfloat16 Bs[NSUB][TJS][SMSTRIDE];
    __shared__ float s_warp[8];
    __shared__ int s_last;

    int tid = threadIdx.x;
    int warp = tid >> 5, lane = tid & 31;

    bool active = (i0 < nI) && (j0 < nJ) &&
                  !(mode == 0 && (j0 + TJS * NSUB - 1) <= i0);

    if (active) {
        const __nv_bfloat16* Abase = g_feat2 + ((size_t)b * NN + i0) * NC;
        const __nv_bfloat16* Bbase =
            g_feat2 + ((size_t)b * NN + (mode ? nI : 0) + j0) * NC;

        // Group 0: A + B0.  Group 1: B1.  Group 2: B2.
#pragma unroll
        for (int c = 0; c < 4; c++) {
            int chunk = tid + c * 256;
            int r = chunk >> 3, col = chunk & 7;
            unsigned dst = (unsigned)__cvta_generic_to_shared(&As[r][col * 8]);
            cpa16(dst, Abase + (size_t)r * NC + col * 8, (i0 + r) < nI);
        }
#pragma unroll
        for (int s = 0; s < NSUB; s++) {
#pragma unroll
            for (int c = 0; c < 2; c++) {
                int chunk = tid + c * 256;
                int r = chunk >> 3, col = chunk & 7;
                int jr = s * TJS + r;
                unsigned dst =
                    (unsigned)__cvta_generic_to_shared(&Bs[s][r][col * 8]);
                cpa16(dst, Bbase + (size_t)jr * NC + col * 8, (j0 + jr) < nJ);
            }
            asm volatile("cp.async.commit_group;\n");
        }

        int mBase = warp * 16;               // warp tile 16 (M) x 64 (N)
        const float K10LOG2E = 14.4269504089f;
        int g = lane >> 2, tq = lane & 3;
        int riB = i0 + mBase + g;
        float sumv = 0.f;

#pragma unroll
        for (int sub = 0; sub < NSUB; sub++) {
            // Wait for this sub's fill group (A rides with sub 0).
            asm volatile("cp.async.wait_group %0;\n" :: "n"(NSUB - 1 - 0 - 0));
            // NOTE: need per-sub constant; handled below via if-chain.
            if (sub == 0) { asm volatile("cp.async.wait_group 2;\n"); }
            else if (sub == 1) { asm volatile("cp.async.wait_group 1;\n"); }
            else { asm volatile("cp.async.wait_group 0;\n"); }
            __syncthreads();

            int j0s = j0 + sub * TJS;
            if (j0s >= nJ) break;
            if (mode == 0 && (j0s + TJS - 1) <= i0) continue;  // below diag

            float acc[8][4];
#pragma unroll
            for (int ni = 0; ni < 8; ni++)
#pragma unroll
                for (int e = 0; e < 4; e++) acc[ni][e] = 0.f;

#pragma unroll
            for (int ks = 0; ks < 4; ks++) {
                int k0 = ks * 16;
                unsigned afr[4];
                {
                    unsigned a = (unsigned)__cvta_generic_to_shared(
                        &As[mBase + (lane & 15)][k0 + (lane >> 4) * 8]);
                    ldm_x4(afr, a);
                }
#pragma unroll
                for (int np = 0; np < 4; np++) {
                    unsigned bt[4];
                    unsigned a = (unsigned)__cvta_generic_to_shared(
                        &Bs[sub][np * 16 + (lane & 7) + 8 * (lane >> 4)]
                           [k0 + ((lane >> 3) & 1) * 8]);
                    ldm_x4(bt, a);
                    mma_bf16(acc[np * 2 + 0], afr, bt[0], bt[1]);
                    mma_bf16(acc[np * 2 + 1], afr, bt[2], bt[3]);
                }
            }

            int cjB = j0s + tq * 2;
            bool interior = ((i0 + TI) <= nI) && ((j0s + TJS) <= nJ);
            if (mode == 0) {
                if (interior && j0s >= i0 + TI) {
#pragma unroll
                    for (int ni = 0; ni < 8; ni++)
#pragma unroll
                        for (int e = 0; e < 4; e++)
                            sumv += exp2f(acc[ni][e] * K10LOG2E);
                } else {
#pragma unroll
                    for (int ni = 0; ni < 8; ni++) {
#pragma unroll
                        for (int e = 0; e < 4; e++) {
                            int ri = riB + ((e >> 1) ? 8 : 0);
                            int cj = cjB + ni * 8 + (e & 1);
                            if (ri < nI && cj < nJ && cj > ri)
                                sumv += exp2f(acc[ni][e] * K10LOG2E);
                        }
                    }
                }
            } else {
                // 8-way log-product: sim <= 10 => factor <= 2.21e4;
                // 8-way product <= 5.6e34 < fp32 max.
                if (interior) {
#pragma unroll
                    for (int ni = 0; ni < 8; ni += 2) {
                        float p = 1.0f;
#pragma unroll
                        for (int q = 0; q < 2; q++)
#pragma unroll
                            for (int e = 0; e < 4; e++)
                                p *= 1.0f + exp2f(acc[ni + q][e] * K10LOG2E);
                        sumv += __log2f(p);
                    }
                } else {
#pragma unroll
                    for (int ni = 0; ni < 8; ni += 2) {
                        float p = 1.0f;
#pragma unroll
                        for (int q = 0; q < 2; q++) {
#pragma unroll
                            for (int e = 0; e < 4; e++) {
                                int ri = riB + ((e >> 1) ? 8 : 0);
                                int cj = cjB + (ni + q) * 8 + (e & 1);
                                float ex = exp2f(acc[ni + q][e] * K10LOG2E);
                                bool v = (ri < nI) && (cj < nJ);
                                p *= v ? (1.0f + ex) : 1.0f;
                            }
                        }
                        sumv += __log2f(p);
                    }
                }
            }
        }

#pragma unroll
        for (int o = 16; o; o >>= 1)
            sumv += __shfl_down_sync(0xffffffffu, sumv, o);
        if (lane == 0) s_warp[warp] = sumv;
        __syncthreads();
        if (warp == 0) {
            float v = (lane < 8) ? s_warp[lane] : 0.f;
#pragma unroll
            for (int o = 4; o; o >>= 1)
                v += __shfl_down_sync(0xffffffffu, v, o);
            if (lane == 0) {
                if (mode == 0) atomicAdd(&g_pos[b], 2.0 * (double)v);
                else atomicAdd(&g_neg[b], (double)v * 0.6931471805599453);
            }
        }
    }

    // Completion protocol: EVERY block arrives exactly once.
    __syncthreads();
    if (tid == 0) {
        __threadfence();
        unsigned t = atomicAdd(&g_done, 1u);
        s_last = (t == (unsigned)(TOTAL_BLOCKS - 1)) ? 1 : 0;
    }
    __syncthreads();

    if (s_last) {
        if (tid == 0) {
            __threadfence();     // acquire all g_pos/g_neg
            g_done = 0;          // self-reset for graph replay
        }
        __syncthreads();
        if (warp == 0) {
            double per = 0.0, vcnt = 0.0;
            if (lane < NB) {
                int nn = g_cnt[lane];
                int na = NN - nn;
                bool valid = (nn >= 10) && (na >= 5);
                double pc = (double)nn * (double)nn - (double)nn;
                double cc = (double)nn * (double)na;
                double pm = g_pos[lane] / (pc > 1.0 ? pc : 1.0);
                double pl = -log(pm + 1e-6);
                double nl = g_neg[lane] / (cc > 1.0 ? cc : 1.0);
                if (valid) { per = pl + nl; vcnt = 1.0; }
            }
#pragma unroll
            for (int o = 16; o; o >>= 1) {
                per += __shfl_down_sync(0xffffffffu, per, o);
                vcnt += __shfl_down_sync(0xffffffffu, vcnt, o);
            }
            if (lane == 0) out[0] = (float)(per / (vcnt > 1.0 ? vcnt : 1.0));
        }
    }
}

extern "C" void kernel_launch(void* const* d_in, const int* in_sizes, int n_in,
                              void* d_out, int out_size) {
    const float* feat = (const float*)d_in[0];   // [8,64,4000,1]
    const float* prob = (const float*)d_in[1];   // [8,1,4000,1]

    compact_kernel<<<NB, 256>>>(prob);
    normalize_kernel<<<(NB * NN + 255) / 256, 256>>>(feat);
    dim3 grid(2 * JTS, IT32, NB);   // (mode|jstrip, it, b)
    mma_loss_kernel<<<grid, 256>>>((float*)d_out);
}

// round 16
// speedup vs baseline: 1.2940x; 1.2940x over previous
#include <cuda_runtime.h>
#include <cuda_bf16.h>
#include <stdint.h>
#include <math.h>

#define NB 8
#define NC 64
#define NN 4000
#define TI 128          // i-tile rows
#define TJS 64          // j-subtile width
#define NSUB 3          // j-subtiles per block (strip = 192; smem 46.1KB < 48KB)
#define JTS 21          // ceil(4000/192) j-strips per mode
#define SMSTRIDE 72     // 64 bf16 + 8 pad (144B rows; ldmatrix conflict-free)
#define PER 16          // indices per thread in compact

// Scratch (device globals; no allocations allowed)
__device__ __nv_bfloat16 g_feat2[NB * NN * NC];  // normalized, COMPACTED order
__device__ int           g_pmap[NB * NN];
__device__ int           g_cnt[NB];
__device__ double        g_pos[NB];
__device__ double        g_neg[NB];

// ---------------------------------------------------------------------------
// Kernel 1: classify + position map via ONE block-scan (deterministic).
// ---------------------------------------------------------------------------
__global__ void compact_kernel(const float* __restrict__ prob) {
    int b = blockIdx.x;
    int tid = threadIdx.x;
    int lane = tid & 31, wid = tid >> 5;
    int start = tid * PER;

    const float* pb = prob + b * NN;
    unsigned mask = 0;
    int cN = 0;
#pragma unroll
    for (int k = 0; k < PER; k++) {
        int idx = start + k;
        if (idx < NN && pb[idx] < 0.5f) { mask |= (1u << k); cN++; }
    }
    int nv = (start < NN) ? min(PER, NN - start) : 0;
    int cA = nv - cN;

    int sNi = cN, sAi = cA;
#pragma unroll
    for (int o = 1; o < 32; o <<= 1) {
        int xn = __shfl_up_sync(0xffffffffu, sNi, o);
        int xa = __shfl_up_sync(0xffffffffu, sAi, o);
        if (lane >= o) { sNi += xn; sAi += xa; }
    }
    __shared__ int wN[8], wA[8];
    if (lane == 31) { wN[wid] = sNi; wA[wid] = sAi; }
    __syncthreads();
    int baseWN = 0, baseWA = 0, totN = 0;
    for (int w = 0; w < 8; w++) {
        if (w < wid) { baseWN += wN[w]; baseWA += wA[w]; }
        totN += wN[w];
    }
    int offN = baseWN + sNi - cN;
    int offA = baseWA + sAi - cA;

    int* pm = g_pmap + b * NN;
#pragma unroll
    for (int k = 0; k < PER; k++) {
        int idx = start + k;
        if (idx >= NN) break;
        if (mask & (1u << k)) pm[idx] = offN++;
        else                  pm[idx] = ~(offA++);
    }
    if (tid == 0) {
        g_cnt[b] = totN;
        g_pos[b] = 0.0;
        g_neg[b] = 0.0;
    }
}

// ---------------------------------------------------------------------------
// Kernel 2: row-normalize (fp32) -> bf16, writing to COMPACTED row position.
// ---------------------------------------------------------------------------
__global__ void normalize_kernel(const float* __restrict__ feat) {
    int row = blockIdx.x * blockDim.x + threadIdx.x;
    if (row >= NB * NN) return;
    int b = row / NN;
    int n = row - b * NN;
    const float* src = feat + (size_t)b * NC * NN + n;
    float v[NC];
    float ss = 0.f;
#pragma unroll
    for (int c = 0; c < NC; c++) {
        float x = src[(size_t)c * NN];
        v[c] = x;
        ss += x * x;
    }
    float inv = 1.0f / fmaxf(sqrtf(ss), 1e-12f);
    int pm = g_pmap[b * NN + n];
    int dstRow = (pm >= 0) ? pm : (g_cnt[b] + ~pm);
    __nv_bfloat16* dst = g_feat2 + ((size_t)b * NN + dstRow) * NC;
#pragma unroll
    for (int c = 0; c < NC; c++) dst[c] = __float2bfloat16(v[c] * inv);
}

// ---------------------------------------------------------------------------
// Merged fused GEMM + loss. Each block: one 128-row A tile x THREE 64-wide
// B subtiles (A smem reused). mode 0: upper triangle, sum exp, x2.
// mode 1: softplus via 8-way log-product (1.125 MUFU/elem).
// ---------------------------------------------------------------------------
__device__ __forceinline__ void cpa16(unsigned dst, const void* src, bool valid) {
    int sz = valid ? 16 : 0;
    asm volatile("cp.async.cg.shared.global [%0], [%1], 16, %2;\n"
                 :: "r"(dst), "l"(src), "r"(sz));
}
__device__ __forceinline__ void ldm_x4(unsigned r[4], unsigned addr) {
    asm volatile("ldmatrix.sync.aligned.m8n8.x4.shared.b16 {%0,%1,%2,%3}, [%4];\n"
                 : "=r"(r[0]), "=r"(r[1]), "=r"(r[2]), "=r"(r[3]) : "r"(addr));
}
__device__ __forceinline__ void mma_bf16(float d[4], const unsigned a[4],
                                         unsigned b0, unsigned b1) {
    asm volatile(
        "mma.sync.aligned.m16n8k16.row.col.f32.bf16.bf16.f32 "
        "{%0,%1,%2,%3}, {%4,%5,%6,%7}, {%8,%9}, {%0,%1,%2,%3};\n"
        : "+f"(d[0]), "+f"(d[1]), "+f"(d[2]), "+f"(d[3])
        : "r"(a[0]), "r"(a[1]), "r"(a[2]), "r"(a[3]), "r"(b0), "r"(b1));
}

__global__ __launch_bounds__(256, 3) void mma_loss_kernel() {
    int b = blockIdx.z;
    int nI = g_cnt[b];
    int mode = (blockIdx.x >= JTS) ? 1 : 0;
    int jt = blockIdx.x - mode * JTS;
    int nJ = mode ? (NN - nI) : nI;
    int i0 = blockIdx.y * TI;
    int j0 = jt * (TJS * NSUB);
    if (i0 >= nI || j0 >= nJ) return;
    // mode 0: skip strips entirely below the diagonal.
    if (mode == 0 && (j0 + TJS * NSUB - 1) <= i0) return;

    __shared__ __nv_bfloat16 As[TI][SMSTRIDE];
    __shared__ __nv_bfloat16 Bs[NSUB][TJS][SMSTRIDE];
    __shared__ float s_warp[8];

    int tid = threadIdx.x;
    const __nv_bfloat16* Abase = g_feat2 + ((size_t)b * NN + i0) * NC;
    const __nv_bfloat16* Bbase =
        g_feat2 + ((size_t)b * NN + (mode ? nI : 0) + j0) * NC;

    // Fills: A = 1024 chunks (4/thread); B = 3 x 512 chunks (6/thread).
#pragma unroll
    for (int c = 0; c < 4; c++) {
        int chunk = tid + c * 256;
        int r = chunk >> 3, col = chunk & 7;
        unsigned dst = (unsigned)__cvta_generic_to_shared(&As[r][col * 8]);
        cpa16(dst, Abase + (size_t)r * NC + col * 8, (i0 + r) < nI);
    }
#pragma unroll
    for (int s = 0; s < NSUB; s++) {
#pragma unroll
        for (int c = 0; c < 2; c++) {
            int chunk = tid + c * 256;
            int r = chunk >> 3, col = chunk & 7;
            int jr = s * TJS + r;
            unsigned dst = (unsigned)__cvta_generic_to_shared(&Bs[s][r][col * 8]);
            cpa16(dst, Bbase + (size_t)jr * NC + col * 8, (j0 + jr) < nJ);
        }
    }
    asm volatile("cp.async.commit_group;\n");
    asm volatile("cp.async.wait_group 0;\n");
    __syncthreads();

    int warp = tid >> 5, lane = tid & 31;
    int mBase = warp * 16;               // warp tile 16 (M) x 64 (N)
    const float K10LOG2E = 14.4269504089f;
    int g = lane >> 2, tq = lane & 3;
    int riB = i0 + mBase + g;
    float sumv = 0.f;                    // mode0: sum exp; mode1: sum log2 terms

#pragma unroll
    for (int sub = 0; sub < NSUB; sub++) {
        int j0s = j0 + sub * TJS;
        if (j0s >= nJ) break;
        if (mode == 0 && (j0s + TJS - 1) <= i0) continue;  // sub below diag

        float acc[8][4];
#pragma unroll
        for (int ni = 0; ni < 8; ni++)
#pragma unroll
            for (int e = 0; e < 4; e++) acc[ni][e] = 0.f;

#pragma unroll
        for (int ks = 0; ks < 4; ks++) {
            int k0 = ks * 16;
            unsigned afr[4];
            {
                unsigned a = (unsigned)__cvta_generic_to_shared(
                    &As[mBase + (lane & 15)][k0 + (lane >> 4) * 8]);
                ldm_x4(afr, a);
            }
#pragma unroll
            for (int np = 0; np < 4; np++) {
                unsigned bt[4];
                unsigned a = (unsigned)__cvta_generic_to_shared(
                    &Bs[sub][np * 16 + (lane & 7) + 8 * (lane >> 4)]
                       [k0 + ((lane >> 3) & 1) * 8]);
                ldm_x4(bt, a);
                mma_bf16(acc[np * 2 + 0], afr, bt[0], bt[1]);
                mma_bf16(acc[np * 2 + 1], afr, bt[2], bt[3]);
            }
        }

        int cjB = j0s + tq * 2;
        bool interior = ((i0 + TI) <= nI) && ((j0s + TJS) <= nJ);
        if (mode == 0) {
            if (interior && j0s >= i0 + TI) {
#pragma unroll
                for (int ni = 0; ni < 8; ni++)
#pragma unroll
                    for (int e = 0; e < 4; e++)
                        sumv += exp2f(acc[ni][e] * K10LOG2E);
            } else {
#pragma unroll
                for (int ni = 0; ni < 8; ni++) {
#pragma unroll
                    for (int e = 0; e < 4; e++) {
                        int ri = riB + ((e >> 1) ? 8 : 0);
                        int cj = cjB + ni * 8 + (e & 1);
                        if (ri < nI && cj < nJ && cj > ri)
                            sumv += exp2f(acc[ni][e] * K10LOG2E);
                    }
                }
            }
        } else {
            // 8-way log-product: sum log2(1+ex) = log2(prod (1+ex)).
            // sim <= 10 => factor <= 2.21e4; 8-way product <= 5.6e34 < fp32 max.
            if (interior) {
#pragma unroll
                for (int ni = 0; ni < 8; ni += 2) {
                    float p = 1.0f;
#pragma unroll
                    for (int q = 0; q < 2; q++)
#pragma unroll
                        for (int e = 0; e < 4; e++)
                            p *= 1.0f + exp2f(acc[ni + q][e] * K10LOG2E);
                    sumv += __log2f(p);
                }
            } else {
#pragma unroll
                for (int ni = 0; ni < 8; ni += 2) {
                    float p = 1.0f;
#pragma unroll
                    for (int q = 0; q < 2; q++) {
#pragma unroll
                        for (int e = 0; e < 4; e++) {
                            int ri = riB + ((e >> 1) ? 8 : 0);
                            int cj = cjB + (ni + q) * 8 + (e & 1);
                            float ex = exp2f(acc[ni + q][e] * K10LOG2E);
                            bool v = (ri < nI) && (cj < nJ);
                            p *= v ? (1.0f + ex) : 1.0f;
                        }
                    }
                    sumv += __log2f(p);
                }
            }
        }
    }

#pragma unroll
    for (int o = 16; o; o >>= 1)
        sumv += __shfl_down_sync(0xffffffffu, sumv, o);
    if (lane == 0) s_warp[warp] = sumv;
    __syncthreads();
    if (warp == 0) {
        float v = (lane < 8) ? s_warp[lane] : 0.f;
#pragma unroll
        for (int o = 4; o; o >>= 1)
            v += __shfl_down_sync(0xffffffffu, v, o);
        if (lane == 0) {
            if (mode == 0) atomicAdd(&g_pos[b], 2.0 * (double)v);  // symmetry
            else atomicAdd(&g_neg[b], (double)v * 0.6931471805599453);  // ln2
        }
    }
}

// ---------------------------------------------------------------------------
// Finalize scalar
// ---------------------------------------------------------------------------
__global__ void finalize_kernel(float* __restrict__ out) {
    int tid = threadIdx.x;
    double per = 0.0, vcnt = 0.0;
    if (tid < NB) {
        int nn = g_cnt[tid];
        int na = NN - nn;
        bool valid = (nn >= 10) && (na >= 5);
        double pc = (double)nn * (double)nn - (double)nn;
        double cc = (double)nn * (double)na;
        double pm = g_pos[tid] / (pc > 1.0 ? pc : 1.0);
        double pl = -log(pm + 1e-6);
        double nl = g_neg[tid] / (cc > 1.0 ? cc : 1.0);
        if (valid) { per = pl + nl; vcnt = 1.0; }
    }
    for (int o = 16; o; o >>= 1) {
        per += __shfl_down_sync(0xffffffffu, per, o);
        vcnt += __shfl_down_sync(0xffffffffu, vcnt, o);
    }
    if (tid == 0) out[0] = (float)(per / (vcnt > 1.0 ? vcnt : 1.0));
}

extern "C" void kernel_launch(void* const* d_in, const int* in_sizes, int n_in,
                              void* d_out, int out_size) {
    const float* feat = (const float*)d_in[0];   // [8,64,4000,1]
    const float* prob = (const float*)d_in[1];   // [8,1,4000,1]

    compact_kernel<<<NB, 256>>>(prob);
    normalize_kernel<<<(NB * NN + 255) / 256, 256>>>(feat);
    dim3 grid(2 * JTS, (NN + TI - 1) / TI, NB);   // (mode|jstrip, it, b)
    mma_loss_kernel<<<grid, 256>>>();
    finalize_kernel<<<1, 32>>>((float*)d_out);
}

// round 17
// speedup vs baseline: 1.3363x; 1.0327x over previous
#include <cuda_runtime.h>
#include <cuda_bf16.h>
#include <stdint.h>
#include <math.h>

#define NB 8
#define NC 64
#define NN 4000
#define TI 128          // i-tile rows
#define TJS 64          // j-subtile width
#define NSUB 3          // j-subtiles per block (strip = 192; smem 46.1KB < 48KB)
#define JTS 21          // ceil(4000/192) j-strips per mode
#define SMSTRIDE 72     // 64 bf16 + 8 pad (144B rows; ldmatrix conflict-free)
#define PER 16          // indices per thread in the scan (256*16 = 4096 >= NN)

// Scratch (device globals; no allocations allowed)
__device__ __nv_bfloat16 g_feat2[NB * NN * NC];  // normalized, COMPACTED order
__device__ int           g_cnt[NB];
__device__ double        g_pos[NB];
__device__ double        g_neg[NB];

// ---------------------------------------------------------------------------
// Kernel 1: fused classify-scan + normalize + compacted scatter.
// Grid (16, NB): each block redundantly scans its batch's 4000 probs
// (deterministic block-scan, identical result in every block), then
// normalizes its 256 rows and writes them to compacted positions.
// ---------------------------------------------------------------------------
__global__ void prep_kernel(const float* __restrict__ feat,
                            const float* __restrict__ prob) {
    int b = blockIdx.y;
    int tid = threadIdx.x;
    int lane = tid & 31, wid = tid >> 5;
    int start = tid * PER;

    // ---- Phase 1: full-batch scan (every block, identical result) ----
    const float* pb = prob + b * NN;
    unsigned mask = 0;
    int cN = 0;
#pragma unroll
    for (int k = 0; k < PER; k++) {
        int idx = start + k;
        if (idx < NN && pb[idx] < 0.5f) { mask |= (1u << k); cN++; }
    }
    int nv = (start < NN) ? min(PER, NN - start) : 0;
    int cA = nv - cN;

    int sNi = cN, sAi = cA;
#pragma unroll
    for (int o = 1; o < 32; o <<= 1) {
        int xn = __shfl_up_sync(0xffffffffu, sNi, o);
        int xa = __shfl_up_sync(0xffffffffu, sAi, o);
        if (lane >= o) { sNi += xn; sAi += xa; }
    }
    __shared__ int wN[8], wA[8];
    __shared__ int s_dst[4096];
    if (lane == 31) { wN[wid] = sNi; wA[wid] = sAi; }
    __syncthreads();
    int baseWN = 0, baseWA = 0, totN = 0;
    for (int w = 0; w < 8; w++) {
        if (w < wid) { baseWN += wN[w]; baseWA += wA[w]; }
        totN += wN[w];
    }
    int offN = baseWN + sNi - cN;
    int offA = baseWA + sAi - cA;

#pragma unroll
    for (int k = 0; k < PER; k++) {
        int idx = start + k;
        if (idx >= NN) break;
        if (mask & (1u << k)) s_dst[idx] = offN++;
        else                  s_dst[idx] = totN + offA++;
    }
    if (blockIdx.x == 0 && tid == 0) {
        g_cnt[b] = totN;
        g_pos[b] = 0.0;
        g_neg[b] = 0.0;
    }
    __syncthreads();

    // ---- Phase 2: normalize this block's 256 rows, scatter compacted ----
    int n = blockIdx.x * 256 + tid;
    if (n >= NN) return;
    const float* src = feat + (size_t)b * NC * NN + n;
    float v[NC];
    float ss = 0.f;
#pragma unroll
    for (int c = 0; c < NC; c++) {
        float x = src[(size_t)c * NN];
        v[c] = x;
        ss += x * x;
    }
    float inv = 1.0f / fmaxf(sqrtf(ss), 1e-12f);
    int dstRow = s_dst[n];
    __nv_bfloat16* dst = g_feat2 + ((size_t)b * NN + dstRow) * NC;
#pragma unroll
    for (int c = 0; c < NC; c++) dst[c] = __float2bfloat16(v[c] * inv);
}

// ---------------------------------------------------------------------------
// Merged fused GEMM + loss (unchanged from R16 baseline, 69.7us).
// mode 0: upper triangle, sum exp, x2.  mode 1: softplus, 8-way log-product.
// ---------------------------------------------------------------------------
__device__ __forceinline__ void cpa16(unsigned dst, const void* src, bool valid) {
    int sz = valid ? 16 : 0;
    asm volatile("cp.async.cg.shared.global [%0], [%1], 16, %2;\n"
                 :: "r"(dst), "l"(src), "r"(sz));
}
__device__ __forceinline__ void ldm_x4(unsigned r[4], unsigned addr) {
    asm volatile("ldmatrix.sync.aligned.m8n8.x4.shared.b16 {%0,%1,%2,%3}, [%4];\n"
                 : "=r"(r[0]), "=r"(r[1]), "=r"(r[2]), "=r"(r[3]) : "r"(addr));
}
__device__ __forceinline__ void mma_bf16(float d[4], const unsigned a[4],
                                         unsigned b0, unsigned b1) {
    asm volatile(
        "mma.sync.aligned.m16n8k16.row.col.f32.bf16.bf16.f32 "
        "{%0,%1,%2,%3}, {%4,%5,%6,%7}, {%8,%9}, {%0,%1,%2,%3};\n"
        : "+f"(d[0]), "+f"(d[1]), "+f"(d[2]), "+f"(d[3])
        : "r"(a[0]), "r"(a[1]), "r"(a[2]), "r"(a[3]), "r"(b0), "r"(b1));
}

__global__ __launch_bounds__(256, 3) void mma_loss_kernel() {
    int b = blockIdx.z;
    int nI = g_cnt[b];
    int mode = (blockIdx.x >= JTS) ? 1 : 0;
    int jt = blockIdx.x - mode * JTS;
    int nJ = mode ? (NN - nI) : nI;
    int i0 = blockIdx.y * TI;
    int j0 = jt * (TJS * NSUB);
    if (i0 >= nI || j0 >= nJ) return;
    if (mode == 0 && (j0 + TJS * NSUB - 1) <= i0) return;

    __shared__ __nv_bfloat16 As[TI][SMSTRIDE];
    __shared__ __nv_bfloat16 Bs[NSUB][TJS][SMSTRIDE];
    __shared__ float s_warp[8];

    int tid = threadIdx.x;
    const __nv_bfloat16* Abase = g_feat2 + ((size_t)b * NN + i0) * NC;
    const __nv_bfloat16* Bbase =
        g_feat2 + ((size_t)b * NN + (mode ? nI : 0) + j0) * NC;

#pragma unroll
    for (int c = 0; c < 4; c++) {
        int chunk = tid + c * 256;
        int r = chunk >> 3, col = chunk & 7;
        unsigned dst = (unsigned)__cvta_generic_to_shared(&As[r][col * 8]);
        cpa16(dst, Abase + (size_t)r * NC + col * 8, (i0 + r) < nI);
    }
#pragma unroll
    for (int s = 0; s < NSUB; s++) {
#pragma unroll
        for (int c = 0; c < 2; c++) {
            int chunk = tid + c * 256;
            int r = chunk >> 3, col = chunk & 7;
            int jr = s * TJS + r;
            unsigned dst = (unsigned)__cvta_generic_to_shared(&Bs[s][r][col * 8]);
            cpa16(dst, Bbase + (size_t)jr * NC + col * 8, (j0 + jr) < nJ);
        }
    }
    asm volatile("cp.async.commit_group;\n");
    asm volatile("cp.async.wait_group 0;\n");
    __syncthreads();

    int warp = tid >> 5, lane = tid & 31;
    int mBase = warp * 16;               // warp tile 16 (M) x 64 (N)
    const float K10LOG2E = 14.4269504089f;
    int g = lane >> 2, tq = lane & 3;
    int riB = i0 + mBase + g;
    float sumv = 0.f;

#pragma unroll
    for (int sub = 0; sub < NSUB; sub++) {
        int j0s = j0 + sub * TJS;
        if (j0s >= nJ) break;
        if (mode == 0 && (j0s + TJS - 1) <= i0) continue;

        float acc[8][4];
#pragma unroll
        for (int ni = 0; ni < 8; ni++)
#pragma unroll
            for (int e = 0; e < 4; e++) acc[ni][e] = 0.f;

#pragma unroll
        for (int ks = 0; ks < 4; ks++) {
            int k0 = ks * 16;
            unsigned afr[4];
            {
                unsigned a = (unsigned)__cvta_generic_to_shared(
                    &As[mBase + (lane & 15)][k0 + (lane >> 4) * 8]);
                ldm_x4(afr, a);
            }
#pragma unroll
            for (int np = 0; np < 4; np++) {
                unsigned bt[4];
                unsigned a = (unsigned)__cvta_generic_to_shared(
                    &Bs[sub][np * 16 + (lane & 7) + 8 * (lane >> 4)]
                       [k0 + ((lane >> 3) & 1) * 8]);
                ldm_x4(bt, a);
                mma_bf16(acc[np * 2 + 0], afr, bt[0], bt[1]);
                mma_bf16(acc[np * 2 + 1], afr, bt[2], bt[3]);
            }
        }

        int cjB = j0s + tq * 2;
        bool interior = ((i0 + TI) <= nI) && ((j0s + TJS) <= nJ);
        if (mode == 0) {
            if (interior && j0s >= i0 + TI) {
#pragma unroll
                for (int ni = 0; ni < 8; ni++)
#pragma unroll
                    for (int e = 0; e < 4; e++)
                        sumv += exp2f(acc[ni][e] * K10LOG2E);
            } else {
#pragma unroll
                for (int ni = 0; ni < 8; ni++) {
#pragma unroll
                    for (int e = 0; e < 4; e++) {
                        int ri = riB + ((e >> 1) ? 8 : 0);
                        int cj = cjB + ni * 8 + (e & 1);
                        if (ri < nI && cj < nJ && cj > ri)
                            sumv += exp2f(acc[ni][e] * K10LOG2E);
                    }
                }
            }
        } else {
            // 8-way log-product: sim <= 10 => factor <= 2.21e4;
            // 8-way product <= 5.6e34 < fp32 max.
            if (interior) {
#pragma unroll
                for (int ni = 0; ni < 8; ni += 2) {
                    float p = 1.0f;
#pragma unroll
                    for (int q = 0; q < 2; q++)
#pragma unroll
                        for (int e = 0; e < 4; e++)
                            p *= 1.0f + exp2f(acc[ni + q][e] * K10LOG2E);
                    sumv += __log2f(p);
                }
            } else {
#pragma unroll
                for (int ni = 0; ni < 8; ni += 2) {
                    float p = 1.0f;
#pragma unroll
                    for (int q = 0; q < 2; q++) {
#pragma unroll
                        for (int e = 0; e < 4; e++) {
                            int ri = riB + ((e >> 1) ? 8 : 0);
                            int cj = cjB + (ni + q) * 8 + (e & 1);
                            float ex = exp2f(acc[ni + q][e] * K10LOG2E);
                            bool v = (ri < nI) && (cj < nJ);
                            p *= v ? (1.0f + ex) : 1.0f;
                        }
                    }
                    sumv += __log2f(p);
                }
            }
        }
    }

#pragma unroll
    for (int o = 16; o; o >>= 1)
        sumv += __shfl_down_sync(0xffffffffu, sumv, o);
    if (lane == 0) s_warp[warp] = sumv;
    __syncthreads();
    if (warp == 0) {
        float v = (lane < 8) ? s_warp[lane] : 0.f;
#pragma unroll
        for (int o = 4; o; o >>= 1)
            v += __shfl_down_sync(0xffffffffu, v, o);
        if (lane == 0) {
            if (mode == 0) atomicAdd(&g_pos[b], 2.0 * (double)v);  // symmetry
            else atomicAdd(&g_neg[b], (double)v * 0.6931471805599453);  // ln2
        }
    }
}

// ---------------------------------------------------------------------------
// Finalize scalar
// ---------------------------------------------------------------------------
__global__ void finalize_kernel(float* __restrict__ out) {
    int tid = threadIdx.x;
    double per = 0.0, vcnt = 0.0;
    if (tid < NB) {
        int nn = g_cnt[tid];
        int na = NN - nn;
        bool valid = (nn >= 10) && (na >= 5);
        double pc = (double)nn * (double)nn - (double)nn;
        double cc = (double)nn * (double)na;
        double pm = g_pos[tid] / (pc > 1.0 ? pc : 1.0);
        double pl = -log(pm + 1e-6);
        double nl = g_neg[tid] / (cc > 1.0 ? cc : 1.0);
        if (valid) { per = pl + nl; vcnt = 1.0; }
    }
    for (int o = 16; o; o >>= 1) {
        per += __shfl_down_sync(0xffffffffu, per, o);
        vcnt += __shfl_down_sync(0xffffffffu, vcnt, o);
    }
    if (tid == 0) out[0] = (float)(per / (vcnt > 1.0 ? vcnt : 1.0));
}

extern "C" void kernel_launch(void* const* d_in, const int* in_sizes, int n_in,
                              void* d_out, int out_size) {
    const float* feat = (const float*)d_in[0];   // [8,64,4000,1]
    const float* prob = (const float*)d_in[1];   // [8,1,4000,1]

    dim3 pgrid((NN + 255) / 256, NB);            // 16 x 8 blocks
    prep_kernel<<<pgrid, 256>>>(feat, prob);
    dim3 grid(2 * JTS, (NN + TI - 1) / TI, NB);  // (mode|jstrip, it, b)
    mma_loss_kernel<<<grid, 256>>>();
    finalize_kernel<<<1, 32>>>((float*)d_out);
}